// round 15
// baseline (speedup 1.0000x reference)
#include <cuda_runtime.h>
#include <cuda_bf16.h>
#include <cuda_fp16.h>
#include <cstdint>

// Fixed problem shapes
#define Bb 2
#define Nn 2048
#define Dd 1024
#define Hh 16
#define HD 64
#define BN_ROWS 4096
#define QKV_COLS 3072
#define NH (Bb * Hh)
#define HSZ (Nn * HD)

// Scratch (device globals: allocation-guard safe)
__device__ float g_qkv[BN_ROWS * QKV_COLS];
__device__ __nv_bfloat16 g_xh[BN_ROWS * Dd], g_xl[BN_ROWS * Dd];
__device__ __nv_bfloat16 g_wqh[QKV_COLS * Dd], g_wql[QKV_COLS * Dd];
__device__ __nv_bfloat16 g_woh[Dd * Dd], g_wol[Dd * Dd];
__device__ __nv_bfloat16 g_ctxh[BN_ROWS * Dd], g_ctxl[BN_ROWS * Dd];
__device__ __half g_q16h[NH * HSZ];
__device__ __half g_k16h[NH * HSZ], g_k16l[NH * HSZ];
__device__ __half g_v16h[NH * HSZ];                     // [bh][hd][n]

// ---------------------------------------------------------------------------
// helpers
// ---------------------------------------------------------------------------
__device__ __forceinline__ uint32_t smem_u32(const void* p) {
    uint32_t a;
    asm("{ .reg .u64 t; cvta.to.shared.u64 t, %1; cvt.u32.u64 %0, t; }" : "=r"(a) : "l"(p));
    return a;
}
__device__ __forceinline__ uint32_t h2_as_u32(__half2 h) {
    return *reinterpret_cast<uint32_t*>(&h);
}

#define CP16(dst, src) \
    asm volatile("cp.async.cg.shared.global [%0], [%1], 16;" :: "r"(dst), "l"(src))
#define CP_COMMIT() asm volatile("cp.async.commit_group;" ::: "memory")
#define CP_WAIT(n)  asm volatile("cp.async.wait_group %0;" :: "n"(n) : "memory")

#define LDSM_X4(r0, r1, r2, r3, addr) \
    asm volatile("ldmatrix.sync.aligned.m8n8.x4.shared.b16 {%0,%1,%2,%3}, [%4];" \
                 : "=r"(r0), "=r"(r1), "=r"(r2), "=r"(r3) : "r"(addr))

#define MMA_BF16(d, a, b0, b1) \
    asm volatile("mma.sync.aligned.m16n8k16.row.col.f32.bf16.bf16.f32 " \
                 "{%0,%1,%2,%3},{%4,%5,%6,%7},{%8,%9},{%0,%1,%2,%3};" \
                 : "+f"((d)[0]), "+f"((d)[1]), "+f"((d)[2]), "+f"((d)[3]) \
                 : "r"((a)[0]), "r"((a)[1]), "r"((a)[2]), "r"((a)[3]), \
                   "r"(b0), "r"(b1))

#define MMA_FP16(d, a, b0, b1) \
    asm volatile("mma.sync.aligned.m16n8k16.row.col.f32.f16.f16.f32 " \
                 "{%0,%1,%2,%3},{%4,%5,%6,%7},{%8,%9},{%0,%1,%2,%3};" \
                 : "+f"((d)[0]), "+f"((d)[1]), "+f"((d)[2]), "+f"((d)[3]) \
                 : "r"((a)[0]), "r"((a)[1]), "r"((a)[2]), "r"((a)[3]), \
                   "r"(b0), "r"(b1))

// ---------------------------------------------------------------------------
// prep1: elementwise fp32 -> bf16 hi/lo split
// ---------------------------------------------------------------------------
__global__ __launch_bounds__(256)
void split_bf16(const float* __restrict__ in, __nv_bfloat16* __restrict__ oh,
                __nv_bfloat16* __restrict__ ol, int n4) {
    const int i = blockIdx.x * 256 + threadIdx.x;
    if (i >= n4) return;
    const float4 v = reinterpret_cast<const float4*>(in)[i];
    float f[4] = {v.x, v.y, v.z, v.w};
    __nv_bfloat16 h[4], l[4];
#pragma unroll
    for (int e = 0; e < 4; e++) {
        h[e] = __float2bfloat16_rn(f[e]);
        l[e] = __float2bfloat16_rn(f[e] - __bfloat162float(h[e]));
    }
    __nv_bfloat162 h01; h01.x = h[0]; h01.y = h[1];
    __nv_bfloat162 h23; h23.x = h[2]; h23.y = h[3];
    __nv_bfloat162 l01; l01.x = l[0]; l01.y = l[1];
    __nv_bfloat162 l23; l23.x = l[2]; l23.y = l[3];
    reinterpret_cast<__nv_bfloat162*>(oh)[2 * i]     = h01;
    reinterpret_cast<__nv_bfloat162*>(oh)[2 * i + 1] = h23;
    reinterpret_cast<__nv_bfloat162*>(ol)[2 * i]     = l01;
    reinterpret_cast<__nv_bfloat162*>(ol)[2 * i + 1] = l23;
}

// ---------------------------------------------------------------------------
// prep2: qkv fp32 -> per-head fp16 (Qh scaled 1/8; Kh+Kl split; Vh transposed)
// ---------------------------------------------------------------------------
__global__ __launch_bounds__(128)
void attn_prep(const float* __restrict__ qkv,
               __half* __restrict__ qh,
               __half* __restrict__ kh, __half* __restrict__ kl,
               __half* __restrict__ vh) {
    __shared__ float sv[64][65];
    const int tid = threadIdx.x;
    const int nt = blockIdx.x, bh = blockIdx.y;
    const int b = bh >> 4, h = bh & 15;
    const int n0 = nt * 64;
    const size_t obase = (size_t)bh * HSZ;

#pragma unroll
    for (int p = 0; p < 8; p++) {
        const int idx = p * 128 + tid;
        const int row = idx >> 4, c4 = (idx & 15) * 4;
        const size_t src = (size_t)(b * Nn + n0 + row) * QKV_COLS + h * HD + c4;
        // Q (scaled 1/8, single fp16)
        {
            const float4 v = *reinterpret_cast<const float4*>(&qkv[src]);
            __half h0 = __float2half_rn(v.x * 0.125f);
            __half h1 = __float2half_rn(v.y * 0.125f);
            __half h2 = __float2half_rn(v.z * 0.125f);
            __half h3 = __float2half_rn(v.w * 0.125f);
            const size_t o = obase + (size_t)(n0 + row) * HD + c4;
            *reinterpret_cast<__half2*>(&qh[o])     = __halves2half2(h0, h1);
            *reinterpret_cast<__half2*>(&qh[o + 2]) = __halves2half2(h2, h3);
        }
        // K (fp16 hi/lo split)
        {
            const float4 v = *reinterpret_cast<const float4*>(&qkv[src + Dd]);
            float f[4] = {v.x, v.y, v.z, v.w};
            __half hh[4], ll[4];
#pragma unroll
            for (int e = 0; e < 4; e++) {
                hh[e] = __float2half_rn(f[e]);
                ll[e] = __float2half_rn(f[e] - __half2float(hh[e]));
            }
            const size_t o = obase + (size_t)(n0 + row) * HD + c4;
            *reinterpret_cast<__half2*>(&kh[o])     = __halves2half2(hh[0], hh[1]);
            *reinterpret_cast<__half2*>(&kh[o + 2]) = __halves2half2(hh[2], hh[3]);
            *reinterpret_cast<__half2*>(&kl[o])     = __halves2half2(ll[0], ll[1]);
            *reinterpret_cast<__half2*>(&kl[o + 2]) = __halves2half2(ll[2], ll[3]);
        }
        // V -> smem
        {
            const float4 v = *reinterpret_cast<const float4*>(&qkv[src + 2 * Dd]);
            sv[row][c4 + 0] = v.x; sv[row][c4 + 1] = v.y;
            sv[row][c4 + 2] = v.z; sv[row][c4 + 3] = v.w;
        }
    }
    __syncthreads();
    // V transposed write: [hd][n] (single fp16)
#pragma unroll
    for (int p = 0; p < 8; p++) {
        const int idx = p * 128 + tid;
        const int hd = idx >> 4, oc4 = (idx & 15) * 4;
        __half h0 = __float2half_rn(sv[oc4 + 0][hd]);
        __half h1 = __float2half_rn(sv[oc4 + 1][hd]);
        __half h2 = __float2half_rn(sv[oc4 + 2][hd]);
        __half h3 = __float2half_rn(sv[oc4 + 3][hd]);
        const size_t o = obase + (size_t)hd * Nn + n0 + oc4;
        *reinterpret_cast<__half2*>(&vh[o])     = __halves2half2(h0, h1);
        *reinterpret_cast<__half2*>(&vh[o + 2]) = __halves2half2(h2, h3);
    }
}

// ---------------------------------------------------------------------------
// bf16x3 GEMM, cp.async double-buffered (validated R12).
// ---------------------------------------------------------------------------
#define G_AH 0
#define G_AL 10240
#define G_BH 20480
#define G_BL 30720
#define G_SBUF 40960
#define G_SMEM (2 * G_SBUF)

__global__ __launch_bounds__(256, 2)
void gemm_sp(const __nv_bfloat16* __restrict__ Ah, const __nv_bfloat16* __restrict__ Al,
             const __nv_bfloat16* __restrict__ Bh, const __nv_bfloat16* __restrict__ Bl,
             const float* __restrict__ bias, float* __restrict__ C,
             int Nc, int K) {
    extern __shared__ char dsm[];
    const uint32_t sbase = smem_u32(dsm);

    const int tid = threadIdx.x;
    const int row0 = blockIdx.y * 128;
    const int col0 = blockIdx.x * 128;
    const int warp = tid >> 5, lane = tid & 31;
    const int wm = warp & 3, wn = warp >> 2;

    const int quad = lane >> 3, r8 = lane & 7;
    const uint32_t offA = (uint32_t)(((quad & 1) * 8 + r8) * 80 + ((quad >> 1) * 8) * 2);
    const uint32_t offB = (uint32_t)(((quad >> 1) * 8 + r8) * 80 + ((quad & 1) * 8) * 2);
    const uint32_t aHi0 = sbase + G_AH + (uint32_t)(wm * 32 * 80) + offA;
    const uint32_t aLo0 = sbase + G_AL + (uint32_t)(wm * 32 * 80) + offA;
    const uint32_t bHi0 = sbase + G_BH + (uint32_t)(wn * 64 * 80) + offB;
    const uint32_t bLo0 = sbase + G_BL + (uint32_t)(wn * 64 * 80) + offB;

    const int sr0 = tid >> 2, su = tid & 3;

    float acc[2][8][4];
#pragma unroll
    for (int mt = 0; mt < 2; mt++)
#pragma unroll
        for (int j = 0; j < 8; j++)
#pragma unroll
            for (int e = 0; e < 4; e++) acc[mt][j][e] = 0.0f;

    const int nk = K >> 5;

    {
        const uint32_t st = sbase;
#pragma unroll
        for (int p = 0; p < 2; p++) {
            const int row = sr0 + p * 64;
            const uint32_t d = st + (uint32_t)(row * 80 + su * 16);
            const size_t ra = (size_t)(row0 + row) * K + su * 8;
            const size_t rb = (size_t)(col0 + row) * K + su * 8;
            CP16(d + G_AH, &Ah[ra]);
            CP16(d + G_AL, &Al[ra]);
            CP16(d + G_BH, &Bh[rb]);
            CP16(d + G_BL, &Bl[rb]);
        }
        CP_COMMIT();
    }

    for (int ks = 0; ks < nk; ks++) {
        const uint32_t bufOff = (uint32_t)((ks & 1) * G_SBUF);
        if (ks + 1 < nk) {
            const uint32_t st = sbase + (uint32_t)(((ks + 1) & 1) * G_SBUF);
            const int k0 = (ks + 1) * 32;
#pragma unroll
            for (int p = 0; p < 2; p++) {
                const int row = sr0 + p * 64;
                const uint32_t d = st + (uint32_t)(row * 80 + su * 16);
                const size_t ra = (size_t)(row0 + row) * K + k0 + su * 8;
                const size_t rb = (size_t)(col0 + row) * K + k0 + su * 8;
                CP16(d + G_AH, &Ah[ra]);
                CP16(d + G_AL, &Al[ra]);
                CP16(d + G_BH, &Bh[rb]);
                CP16(d + G_BL, &Bl[rb]);
            }
            CP_COMMIT();
            CP_WAIT(1);
        } else {
            CP_WAIT(0);
        }
        __syncthreads();

#pragma unroll
        for (int kc = 0; kc < 2; kc++) {
            const uint32_t kadd = bufOff + (uint32_t)(kc * 32);
            uint32_t ah[2][4], al[2][4], bh[8][2], bl[8][2];
#pragma unroll
            for (int mt = 0; mt < 2; mt++) {
                LDSM_X4(ah[mt][0], ah[mt][1], ah[mt][2], ah[mt][3],
                        aHi0 + (uint32_t)(mt * 16 * 80) + kadd);
                LDSM_X4(al[mt][0], al[mt][1], al[mt][2], al[mt][3],
                        aLo0 + (uint32_t)(mt * 16 * 80) + kadd);
            }
#pragma unroll
            for (int g = 0; g < 4; g++) {
                uint32_t t0, t1, t2, t3;
                LDSM_X4(t0, t1, t2, t3, bHi0 + (uint32_t)(g * 16 * 80) + kadd);
                bh[2 * g][0] = t0; bh[2 * g][1] = t1;
                bh[2 * g + 1][0] = t2; bh[2 * g + 1][1] = t3;
                LDSM_X4(t0, t1, t2, t3, bLo0 + (uint32_t)(g * 16 * 80) + kadd);
                bl[2 * g][0] = t0; bl[2 * g][1] = t1;
                bl[2 * g + 1][0] = t2; bl[2 * g + 1][1] = t3;
            }
#pragma unroll
            for (int mt = 0; mt < 2; mt++)
#pragma unroll
                for (int j = 0; j < 8; j++)
                    MMA_BF16(acc[mt][j], ah[mt], bh[j][0], bh[j][1]);
#pragma unroll
            for (int mt = 0; mt < 2; mt++)
#pragma unroll
                for (int j = 0; j < 8; j++)
                    MMA_BF16(acc[mt][j], ah[mt], bl[j][0], bl[j][1]);
#pragma unroll
            for (int mt = 0; mt < 2; mt++)
#pragma unroll
                for (int j = 0; j < 8; j++)
                    MMA_BF16(acc[mt][j], al[mt], bh[j][0], bh[j][1]);
        }
        __syncthreads();
    }

    const int mrow = row0 + wm * 32 + (lane >> 2);
    const int ncol = col0 + wn * 64 + (lane & 3) * 2;
#pragma unroll
    for (int mt = 0; mt < 2; mt++) {
        const int r_up = mrow + mt * 16;
#pragma unroll
        for (int j = 0; j < 8; j++) {
            const int c = ncol + j * 8;
            const float b0 = bias[c], b1 = bias[c + 1];
            float2 v0 = make_float2(acc[mt][j][0] + b0, acc[mt][j][1] + b1);
            float2 v1 = make_float2(acc[mt][j][2] + b0, acc[mt][j][3] + b1);
            *reinterpret_cast<float2*>(&C[(size_t)r_up * Nc + c]) = v0;
            *reinterpret_cast<float2*>(&C[(size_t)(r_up + 8) * Nc + c]) = v1;
        }
    }
}

// ---------------------------------------------------------------------------
// Tensor-core flash attention.
// S = Qh.Kh + Qh.Kl (2 passes); PV = P x Vh (1 pass).
// Dynamic smem: Q (9216) + 2 bufs x (3 x 9216) = 64512B -> 3 CTAs/SM.
// ---------------------------------------------------------------------------
#define AROW 72
#define ARS  144
#define A_QH 0
#define A_KV 9216
#define A_KH 0
#define A_KL 9216
#define A_VH 18432
#define A_VBUF 27648
#define A_SMEM (A_KV + 2 * A_VBUF)   // 64512

__global__ __launch_bounds__(128)
void attn_tc(const __half* __restrict__ qh,
             const __half* __restrict__ kh, const __half* __restrict__ kl,
             const __half* __restrict__ vh,
             const int* __restrict__ t_idx,
             const unsigned char* __restrict__ mask,
             const float* __restrict__ alpha,
             __nv_bfloat16* __restrict__ ctxh, __nv_bfloat16* __restrict__ ctxl) {
    extern __shared__ char dsm[];
    __shared__ int tks2[2][64];
    const uint32_t sbase = smem_u32(dsm);

    const int qt = blockIdx.x, h = blockIdx.y, b = blockIdx.z;
    const int tid = threadIdx.x, warp = tid >> 5, lane = tid & 31;
    const int q0 = qt * 64;

    const float a_h = alpha[h];
    const size_t bn0 = (size_t)(b * Nn);
    const size_t hb = (size_t)(b * Hh + h) * HSZ;

    const int sr0 = tid >> 3, su = tid & 7;

    // ---- stage Q once ----
#pragma unroll
    for (int p = 0; p < 4; p++) {
        const int idx = p * 128 + tid;
        const int row = idx >> 3, u = idx & 7;
        const size_t src = hb + (size_t)(q0 + row) * HD + u * 8;
        *reinterpret_cast<uint4*>(dsm + A_QH + row * ARS + u * 16) =
            *reinterpret_cast<const uint4*>(&qh[src]);
    }

    const int g8 = lane >> 2;
    const int row_lo = q0 + warp * 16 + g8;
    const int row_hi = row_lo + 8;
    const float tq0 = (float)t_idx[bn0 + row_lo];
    const float tq1 = (float)t_idx[bn0 + row_hi];

    float ctxacc[8][4];
#pragma unroll
    for (int j = 0; j < 8; j++)
#pragma unroll
        for (int e = 0; e < 4; e++) ctxacc[j][e] = 0.0f;
    float lsum0 = 0.0f, lsum1 = 0.0f;
    float m0 = -1e30f, m1 = -1e30f;

    const int quad = lane >> 3, r8 = lane & 7;
    const uint32_t offA = (uint32_t)(((quad & 1) * 8 + r8) * ARS + ((quad >> 1) * 8) * 2);
    const uint32_t offB = (uint32_t)(((quad >> 1) * 8 + r8) * ARS + ((quad & 1) * 8) * 2);
    const uint32_t aQh = sbase + A_QH + (uint32_t)(warp * 16 * ARS) + offA;

    // ---- prologue: prefetch K/V tile 0; stage tks(0) ----
    {
        const uint32_t st = sbase + A_KV;
#pragma unroll
        for (int p = 0; p < 4; p++) {
            const int row = sr0 + p * 16;
            const uint32_t d = st + (uint32_t)(row * ARS + su * 16);
            const size_t srcK = hb + (size_t)row * HD + su * 8;
            const size_t srcV = hb + (size_t)row * Nn + su * 8;
            CP16(d + A_KH, &kh[srcK]);
            CP16(d + A_KL, &kl[srcK]);
            CP16(d + A_VH, &vh[srcV]);
        }
        CP_COMMIT();
        if (tid < 64) tks2[0][tid] = t_idx[bn0 + tid];
    }

    for (int it = 0; it < Nn / 64; it++) {
        const int k0 = it * 64;
        const uint32_t kvOff = (uint32_t)((it & 1) * A_VBUF);

        if (it + 1 < Nn / 64) {
            const int kn = (it + 1) * 64;
            const uint32_t st = sbase + A_KV + (uint32_t)(((it + 1) & 1) * A_VBUF);
#pragma unroll
            for (int p = 0; p < 4; p++) {
                const int row = sr0 + p * 16;
                const uint32_t d = st + (uint32_t)(row * ARS + su * 16);
                const size_t srcK = hb + (size_t)(kn + row) * HD + su * 8;
                const size_t srcV = hb + (size_t)row * Nn + kn + su * 8;
                CP16(d + A_KH, &kh[srcK]);
                CP16(d + A_KL, &kl[srcK]);
                CP16(d + A_VH, &vh[srcV]);
            }
            CP_COMMIT();
            if (tid < 64) tks2[(it + 1) & 1][tid] = t_idx[bn0 + kn + tid];
        }

        int myMask;
        {
            const int row = tid >> 1, half = tid & 1;
            const uint4* mp = reinterpret_cast<const uint4*>(
                &mask[(bn0 + q0 + row) * Nn + k0 + half * 32]);
            uint4 mA = mp[0], mB = mp[1];
            myMask = (mA.x | mA.y | mA.z | mA.w | mB.x | mB.y | mB.z | mB.w) != 0;
        }

        if (it + 1 < Nn / 64) { CP_WAIT(1); } else { CP_WAIT(0); }
        const int tileMasked = __syncthreads_or(myMask);

        const uint32_t bKh = sbase + A_KV + kvOff + A_KH + offB;
        const uint32_t bKl = sbase + A_KV + kvOff + A_KL + offB;
        const uint32_t bVh = sbase + A_KV + kvOff + A_VH + offB;
        const int* tks = tks2[it & 1];

        // ---- S = Qh.Kh + Qh.Kl ----
        float sacc[8][4];
#pragma unroll
        for (int j = 0; j < 8; j++)
#pragma unroll
            for (int e = 0; e < 4; e++) sacc[j][e] = 0.0f;

#pragma unroll
        for (int pass = 0; pass < 2; pass++) {
            const uint32_t bBase = (pass == 1) ? bKl : bKh;
#pragma unroll
            for (int kc = 0; kc < 4; kc++) {
                uint32_t aq[4];
                LDSM_X4(aq[0], aq[1], aq[2], aq[3], aQh + (uint32_t)(kc * 32));
#pragma unroll
                for (int g = 0; g < 4; g++) {
                    uint32_t t0, t1, t2, t3;
                    LDSM_X4(t0, t1, t2, t3, bBase + (uint32_t)(g * 16 * ARS + kc * 32));
                    MMA_FP16(sacc[2 * g], aq, t0, t1);
                    MMA_FP16(sacc[2 * g + 1], aq, t2, t3);
                }
            }
        }

        // ---- bias + tile max ----
        float tmax0 = -1e30f, tmax1 = -1e30f;
#pragma unroll
        for (int j = 0; j < 8; j++) {
            const int c0 = 8 * j + 2 * (lane & 3);
            const float tk0 = (float)tks[c0];
            const float tk1 = (float)tks[c0 + 1];
            sacc[j][0] -= a_h * fmaxf(tq0 - tk0, 0.0f);
            sacc[j][1] -= a_h * fmaxf(tq0 - tk1, 0.0f);
            sacc[j][2] -= a_h * fmaxf(tq1 - tk0, 0.0f);
            sacc[j][3] -= a_h * fmaxf(tq1 - tk1, 0.0f);
            tmax0 = fmaxf(tmax0, fmaxf(sacc[j][0], sacc[j][1]));
            tmax1 = fmaxf(tmax1, fmaxf(sacc[j][2], sacc[j][3]));
        }
        tmax0 = fmaxf(tmax0, __shfl_xor_sync(0xFFFFFFFF, tmax0, 1));
        tmax0 = fmaxf(tmax0, __shfl_xor_sync(0xFFFFFFFF, tmax0, 2));
        tmax1 = fmaxf(tmax1, __shfl_xor_sync(0xFFFFFFFF, tmax1, 1));
        tmax1 = fmaxf(tmax1, __shfl_xor_sync(0xFFFFFFFF, tmax1, 2));

        const float mn0 = fmaxf(m0, tmax0);
        const float mn1 = fmaxf(m1, tmax1);
        const float sc0 = __expf(m0 - mn0);
        const float sc1 = __expf(m1 - mn1);
        m0 = mn0; m1 = mn1;
        lsum0 *= sc0; lsum1 *= sc1;
#pragma unroll
        for (int j = 0; j < 8; j++) {
            ctxacc[j][0] *= sc0; ctxacc[j][1] *= sc0;
            ctxacc[j][2] *= sc1; ctxacc[j][3] *= sc1;
        }

        // ---- exp + mask + pack P ----
        uint32_t pa[4][4];
#pragma unroll
        for (int j = 0; j < 8; j++) {
            const int c0 = 8 * j + 2 * (lane & 3);
            float p0 = __expf(sacc[j][0] - m0);
            float p1 = __expf(sacc[j][1] - m0);
            float p2 = __expf(sacc[j][2] - m1);
            float p3 = __expf(sacc[j][3] - m1);
            if (tileMasked) {
                const unsigned char* mr0 = &mask[(bn0 + row_lo) * Nn + k0 + c0];
                const unsigned char* mr1 = &mask[(bn0 + row_hi) * Nn + k0 + c0];
                p0 = mr0[0] ? 0.0f : p0;
                p1 = mr0[1] ? 0.0f : p1;
                p2 = mr1[0] ? 0.0f : p2;
                p3 = mr1[1] ? 0.0f : p3;
            }
            const __half2 lo_h = __float22half2_rn(make_float2(p0, p1));
            const __half2 hi_h = __float22half2_rn(make_float2(p2, p3));
            const float2 lo_r = __half22float2(lo_h);
            const float2 hi_r = __half22float2(hi_h);
            lsum0 += lo_r.x + lo_r.y;
            lsum1 += hi_r.x + hi_r.y;
            pa[j >> 1][(j & 1) * 2 + 0] = h2_as_u32(lo_h);
            pa[j >> 1][(j & 1) * 2 + 1] = h2_as_u32(hi_h);
        }

        // ---- ctx += P x Vh ----
#pragma unroll
        for (int kc = 0; kc < 4; kc++) {
#pragma unroll
            for (int g = 0; g < 4; g++) {
                uint32_t t0, t1, t2, t3;
                LDSM_X4(t0, t1, t2, t3, bVh + (uint32_t)(g * 16 * ARS + kc * 32));
                MMA_FP16(ctxacc[2 * g], pa[kc], t0, t1);
                MMA_FP16(ctxacc[2 * g + 1], pa[kc], t2, t3);
            }
        }
        __syncthreads();
    }

    lsum0 += __shfl_xor_sync(0xFFFFFFFF, lsum0, 1);
    lsum0 += __shfl_xor_sync(0xFFFFFFFF, lsum0, 2);
    lsum1 += __shfl_xor_sync(0xFFFFFFFF, lsum1, 1);
    lsum1 += __shfl_xor_sync(0xFFFFFFFF, lsum1, 2);
    const float inv0 = (lsum0 > 0.0f) ? (1.0f / lsum0) : 0.0f;
    const float inv1 = (lsum1 > 0.0f) ? (1.0f / lsum1) : 0.0f;

#pragma unroll
    for (int j = 0; j < 8; j++) {
        const int c0 = h * HD + 8 * j + 2 * (lane & 3);
        const float o0 = ctxacc[j][0] * inv0, o1 = ctxacc[j][1] * inv0;
        const float o2 = ctxacc[j][2] * inv1, o3 = ctxacc[j][3] * inv1;
        __nv_bfloat16 h0 = __float2bfloat16_rn(o0), h1 = __float2bfloat16_rn(o1);
        __nv_bfloat16 h2 = __float2bfloat16_rn(o2), h3 = __float2bfloat16_rn(o3);
        __nv_bfloat162 hl; hl.x = h0; hl.y = h1;
        __nv_bfloat162 hh; hh.x = h2; hh.y = h3;
        __nv_bfloat162 ll; ll.x = __float2bfloat16_rn(o0 - __bfloat162float(h0));
        ll.y = __float2bfloat16_rn(o1 - __bfloat162float(h1));
        __nv_bfloat162 lh; lh.x = __float2bfloat16_rn(o2 - __bfloat162float(h2));
        lh.y = __float2bfloat16_rn(o3 - __bfloat162float(h3));
        *reinterpret_cast<__nv_bfloat162*>(&ctxh[(bn0 + row_lo) * Dd + c0]) = hl;
        *reinterpret_cast<__nv_bfloat162*>(&ctxh[(bn0 + row_hi) * Dd + c0]) = hh;
        *reinterpret_cast<__nv_bfloat162*>(&ctxl[(bn0 + row_lo) * Dd + c0]) = ll;
        *reinterpret_cast<__nv_bfloat162*>(&ctxl[(bn0 + row_hi) * Dd + c0]) = lh;
    }
}

// ---------------------------------------------------------------------------
extern "C" void kernel_launch(void* const* d_in, const int* in_sizes, int n_in,
                              void* d_out, int out_size) {
    const float*         X     = (const float*)d_in[0];
    const int*           t_idx = (const int*)d_in[1];
    const unsigned char* mask  = (const unsigned char*)d_in[2];
    const float*         Wqkv  = (const float*)d_in[3];
    const float*         bqkv  = (const float*)d_in[4];
    const float*         Wo    = (const float*)d_in[5];
    const float*         bo    = (const float*)d_in[6];
    const float*         alpha = (const float*)d_in[7];
    float*               out   = (float*)d_out;

    void *qkv_p, *xh_p, *xl_p, *wqh_p, *wql_p, *woh_p, *wol_p, *ctxh_p, *ctxl_p;
    void *qh_p, *kh_p, *kl_p, *vh_p;
    cudaGetSymbolAddress(&qkv_p, g_qkv);
    cudaGetSymbolAddress(&xh_p, g_xh);   cudaGetSymbolAddress(&xl_p, g_xl);
    cudaGetSymbolAddress(&wqh_p, g_wqh); cudaGetSymbolAddress(&wql_p, g_wql);
    cudaGetSymbolAddress(&woh_p, g_woh); cudaGetSymbolAddress(&wol_p, g_wol);
    cudaGetSymbolAddress(&ctxh_p, g_ctxh); cudaGetSymbolAddress(&ctxl_p, g_ctxl);
    cudaGetSymbolAddress(&qh_p, g_q16h);
    cudaGetSymbolAddress(&kh_p, g_k16h); cudaGetSymbolAddress(&kl_p, g_k16l);
    cudaGetSymbolAddress(&vh_p, g_v16h);

    cudaFuncSetAttribute(gemm_sp, cudaFuncAttributeMaxDynamicSharedMemorySize, G_SMEM);
    cudaFuncSetAttribute(attn_tc, cudaFuncAttributeMaxDynamicSharedMemorySize, A_SMEM);

    // prep1: split X, Wqkv, Wo
    split_bf16<<<(BN_ROWS * Dd / 4 + 255) / 256, 256>>>(
        X, (__nv_bfloat16*)xh_p, (__nv_bfloat16*)xl_p, BN_ROWS * Dd / 4);
    split_bf16<<<(QKV_COLS * Dd / 4 + 255) / 256, 256>>>(
        Wqkv, (__nv_bfloat16*)wqh_p, (__nv_bfloat16*)wql_p, QKV_COLS * Dd / 4);
    split_bf16<<<(Dd * Dd / 4 + 255) / 256, 256>>>(
        Wo, (__nv_bfloat16*)woh_p, (__nv_bfloat16*)wol_p, Dd * Dd / 4);

    // 1) QKV projection
    {
        dim3 grid(QKV_COLS / 128, BN_ROWS / 128);
        gemm_sp<<<grid, 256, G_SMEM>>>((__nv_bfloat16*)xh_p, (__nv_bfloat16*)xl_p,
                                       (__nv_bfloat16*)wqh_p, (__nv_bfloat16*)wql_p,
                                       bqkv, (float*)qkv_p, QKV_COLS, Dd);
    }

    // prep2: per-head fp16 (Qh, Kh+Kl, Vh transposed)
    {
        dim3 grid(Nn / 64, NH);
        attn_prep<<<grid, 128>>>((const float*)qkv_p,
                                 (__half*)qh_p,
                                 (__half*)kh_p, (__half*)kl_p,
                                 (__half*)vh_p);
    }

    // 2) Tensor-core flash attention -> ctx (bf16 hi/lo)
    {
        dim3 grid(Nn / 64, Hh, Bb);
        attn_tc<<<grid, 128, A_SMEM>>>((const __half*)qh_p,
                                       (const __half*)kh_p, (const __half*)kl_p,
                                       (const __half*)vh_p,
                                       t_idx, mask, alpha,
                                       (__nv_bfloat16*)ctxh_p, (__nv_bfloat16*)ctxl_p);
    }

    // 3) Output projection
    {
        dim3 grid(Dd / 128, BN_ROWS / 128);
        gemm_sp<<<grid, 256, G_SMEM>>>((__nv_bfloat16*)ctxh_p, (__nv_bfloat16*)ctxl_p,
                                       (__nv_bfloat16*)woh_p, (__nv_bfloat16*)wol_p,
                                       bo, out, Dd, Dd);
    }
}

// round 16
// speedup vs baseline: 1.0030x; 1.0030x over previous
#include <cuda_runtime.h>
#include <cuda_bf16.h>
#include <cuda_fp16.h>
#include <cstdint>

// Fixed problem shapes
#define Bb 2
#define Nn 2048
#define Dd 1024
#define Hh 16
#define HD 64
#define BN_ROWS 4096
#define QKV_COLS 3072
#define NH (Bb * Hh)
#define HSZ (Nn * HD)

// Scratch (device globals: allocation-guard safe)
__device__ float g_qkv[BN_ROWS * QKV_COLS];
__device__ __nv_bfloat16 g_xh[BN_ROWS * Dd], g_xl[BN_ROWS * Dd];
__device__ __nv_bfloat16 g_wqh[QKV_COLS * Dd], g_wql[QKV_COLS * Dd];
__device__ __nv_bfloat16 g_woh[Dd * Dd], g_wol[Dd * Dd];
__device__ __nv_bfloat16 g_ctxh[BN_ROWS * Dd], g_ctxl[BN_ROWS * Dd];
__device__ __half g_q16h[NH * HSZ];
__device__ __half g_k16h[NH * HSZ], g_k16l[NH * HSZ];
__device__ __half g_v16h[NH * HSZ];                     // [bh][hd][n]

// ---------------------------------------------------------------------------
// helpers
// ---------------------------------------------------------------------------
__device__ __forceinline__ uint32_t smem_u32(const void* p) {
    uint32_t a;
    asm("{ .reg .u64 t; cvta.to.shared.u64 t, %1; cvt.u32.u64 %0, t; }" : "=r"(a) : "l"(p));
    return a;
}
__device__ __forceinline__ uint32_t h2_as_u32(__half2 h) {
    return *reinterpret_cast<uint32_t*>(&h);
}

#define CP16(dst, src) \
    asm volatile("cp.async.cg.shared.global [%0], [%1], 16;" :: "r"(dst), "l"(src))
#define CP_COMMIT() asm volatile("cp.async.commit_group;" ::: "memory")
#define CP_WAIT(n)  asm volatile("cp.async.wait_group %0;" :: "n"(n) : "memory")

#define LDSM_X4(r0, r1, r2, r3, addr) \
    asm volatile("ldmatrix.sync.aligned.m8n8.x4.shared.b16 {%0,%1,%2,%3}, [%4];" \
                 : "=r"(r0), "=r"(r1), "=r"(r2), "=r"(r3) : "r"(addr))

#define MMA_BF16(d, a, b0, b1) \
    asm volatile("mma.sync.aligned.m16n8k16.row.col.f32.bf16.bf16.f32 " \
                 "{%0,%1,%2,%3},{%4,%5,%6,%7},{%8,%9},{%0,%1,%2,%3};" \
                 : "+f"((d)[0]), "+f"((d)[1]), "+f"((d)[2]), "+f"((d)[3]) \
                 : "r"((a)[0]), "r"((a)[1]), "r"((a)[2]), "r"((a)[3]), \
                   "r"(b0), "r"(b1))

#define MMA_FP16(d, a, b0, b1) \
    asm volatile("mma.sync.aligned.m16n8k16.row.col.f32.f16.f16.f32 " \
                 "{%0,%1,%2,%3},{%4,%5,%6,%7},{%8,%9},{%0,%1,%2,%3};" \
                 : "+f"((d)[0]), "+f"((d)[1]), "+f"((d)[2]), "+f"((d)[3]) \
                 : "r"((a)[0]), "r"((a)[1]), "r"((a)[2]), "r"((a)[3]), \
                   "r"(b0), "r"(b1))

// ---------------------------------------------------------------------------
// prep1: elementwise fp32 -> bf16 hi/lo split
// ---------------------------------------------------------------------------
__global__ __launch_bounds__(256)
void split_bf16(const float* __restrict__ in, __nv_bfloat16* __restrict__ oh,
                __nv_bfloat16* __restrict__ ol, int n4) {
    const int i = blockIdx.x * 256 + threadIdx.x;
    if (i >= n4) return;
    const float4 v = reinterpret_cast<const float4*>(in)[i];
    float f[4] = {v.x, v.y, v.z, v.w};
    __nv_bfloat16 h[4], l[4];
#pragma unroll
    for (int e = 0; e < 4; e++) {
        h[e] = __float2bfloat16_rn(f[e]);
        l[e] = __float2bfloat16_rn(f[e] - __bfloat162float(h[e]));
    }
    __nv_bfloat162 h01; h01.x = h[0]; h01.y = h[1];
    __nv_bfloat162 h23; h23.x = h[2]; h23.y = h[3];
    __nv_bfloat162 l01; l01.x = l[0]; l01.y = l[1];
    __nv_bfloat162 l23; l23.x = l[2]; l23.y = l[3];
    reinterpret_cast<__nv_bfloat162*>(oh)[2 * i]     = h01;
    reinterpret_cast<__nv_bfloat162*>(oh)[2 * i + 1] = h23;
    reinterpret_cast<__nv_bfloat162*>(ol)[2 * i]     = l01;
    reinterpret_cast<__nv_bfloat162*>(ol)[2 * i + 1] = l23;
}

// ---------------------------------------------------------------------------
// prep2: qkv fp32 -> per-head fp16 (Qh scaled 1/8; Kh+Kl split; Vh transposed)
// ---------------------------------------------------------------------------
__global__ __launch_bounds__(128)
void attn_prep(const float* __restrict__ qkv,
               __half* __restrict__ qh,
               __half* __restrict__ kh, __half* __restrict__ kl,
               __half* __restrict__ vh) {
    __shared__ float sv[64][65];
    const int tid = threadIdx.x;
    const int nt = blockIdx.x, bh = blockIdx.y;
    const int b = bh >> 4, h = bh & 15;
    const int n0 = nt * 64;
    const size_t obase = (size_t)bh * HSZ;

#pragma unroll
    for (int p = 0; p < 8; p++) {
        const int idx = p * 128 + tid;
        const int row = idx >> 4, c4 = (idx & 15) * 4;
        const size_t src = (size_t)(b * Nn + n0 + row) * QKV_COLS + h * HD + c4;
        // Q (scaled 1/8, single fp16)
        {
            const float4 v = *reinterpret_cast<const float4*>(&qkv[src]);
            __half h0 = __float2half_rn(v.x * 0.125f);
            __half h1 = __float2half_rn(v.y * 0.125f);
            __half h2 = __float2half_rn(v.z * 0.125f);
            __half h3 = __float2half_rn(v.w * 0.125f);
            const size_t o = obase + (size_t)(n0 + row) * HD + c4;
            *reinterpret_cast<__half2*>(&qh[o])     = __halves2half2(h0, h1);
            *reinterpret_cast<__half2*>(&qh[o + 2]) = __halves2half2(h2, h3);
        }
        // K (fp16 hi/lo split)
        {
            const float4 v = *reinterpret_cast<const float4*>(&qkv[src + Dd]);
            float f[4] = {v.x, v.y, v.z, v.w};
            __half hh[4], ll[4];
#pragma unroll
            for (int e = 0; e < 4; e++) {
                hh[e] = __float2half_rn(f[e]);
                ll[e] = __float2half_rn(f[e] - __half2float(hh[e]));
            }
            const size_t o = obase + (size_t)(n0 + row) * HD + c4;
            *reinterpret_cast<__half2*>(&kh[o])     = __halves2half2(hh[0], hh[1]);
            *reinterpret_cast<__half2*>(&kh[o + 2]) = __halves2half2(hh[2], hh[3]);
            *reinterpret_cast<__half2*>(&kl[o])     = __halves2half2(ll[0], ll[1]);
            *reinterpret_cast<__half2*>(&kl[o + 2]) = __halves2half2(ll[2], ll[3]);
        }
        // V -> smem
        {
            const float4 v = *reinterpret_cast<const float4*>(&qkv[src + 2 * Dd]);
            sv[row][c4 + 0] = v.x; sv[row][c4 + 1] = v.y;
            sv[row][c4 + 2] = v.z; sv[row][c4 + 3] = v.w;
        }
    }
    __syncthreads();
    // V transposed write: [hd][n] (single fp16)
#pragma unroll
    for (int p = 0; p < 8; p++) {
        const int idx = p * 128 + tid;
        const int hd = idx >> 4, oc4 = (idx & 15) * 4;
        __half h0 = __float2half_rn(sv[oc4 + 0][hd]);
        __half h1 = __float2half_rn(sv[oc4 + 1][hd]);
        __half h2 = __float2half_rn(sv[oc4 + 2][hd]);
        __half h3 = __float2half_rn(sv[oc4 + 3][hd]);
        const size_t o = obase + (size_t)hd * Nn + n0 + oc4;
        *reinterpret_cast<__half2*>(&vh[o])     = __halves2half2(h0, h1);
        *reinterpret_cast<__half2*>(&vh[o + 2]) = __halves2half2(h2, h3);
    }
}

// ---------------------------------------------------------------------------
// bf16x3 GEMM, cp.async double-buffered (validated R12).
// ---------------------------------------------------------------------------
#define G_AH 0
#define G_AL 10240
#define G_BH 20480
#define G_BL 30720
#define G_SBUF 40960
#define G_SMEM (2 * G_SBUF)

__global__ __launch_bounds__(256, 2)
void gemm_sp(const __nv_bfloat16* __restrict__ Ah, const __nv_bfloat16* __restrict__ Al,
             const __nv_bfloat16* __restrict__ Bh, const __nv_bfloat16* __restrict__ Bl,
             const float* __restrict__ bias, float* __restrict__ C,
             int Nc, int K) {
    extern __shared__ char dsm[];
    const uint32_t sbase = smem_u32(dsm);

    const int tid = threadIdx.x;
    const int row0 = blockIdx.y * 128;
    const int col0 = blockIdx.x * 128;
    const int warp = tid >> 5, lane = tid & 31;
    const int wm = warp & 3, wn = warp >> 2;

    const int quad = lane >> 3, r8 = lane & 7;
    const uint32_t offA = (uint32_t)(((quad & 1) * 8 + r8) * 80 + ((quad >> 1) * 8) * 2);
    const uint32_t offB = (uint32_t)(((quad >> 1) * 8 + r8) * 80 + ((quad & 1) * 8) * 2);
    const uint32_t aHi0 = sbase + G_AH + (uint32_t)(wm * 32 * 80) + offA;
    const uint32_t aLo0 = sbase + G_AL + (uint32_t)(wm * 32 * 80) + offA;
    const uint32_t bHi0 = sbase + G_BH + (uint32_t)(wn * 64 * 80) + offB;
    const uint32_t bLo0 = sbase + G_BL + (uint32_t)(wn * 64 * 80) + offB;

    const int sr0 = tid >> 2, su = tid & 3;

    float acc[2][8][4];
#pragma unroll
    for (int mt = 0; mt < 2; mt++)
#pragma unroll
        for (int j = 0; j < 8; j++)
#pragma unroll
            for (int e = 0; e < 4; e++) acc[mt][j][e] = 0.0f;

    const int nk = K >> 5;

    {
        const uint32_t st = sbase;
#pragma unroll
        for (int p = 0; p < 2; p++) {
            const int row = sr0 + p * 64;
            const uint32_t d = st + (uint32_t)(row * 80 + su * 16);
            const size_t ra = (size_t)(row0 + row) * K + su * 8;
            const size_t rb = (size_t)(col0 + row) * K + su * 8;
            CP16(d + G_AH, &Ah[ra]);
            CP16(d + G_AL, &Al[ra]);
            CP16(d + G_BH, &Bh[rb]);
            CP16(d + G_BL, &Bl[rb]);
        }
        CP_COMMIT();
    }

    for (int ks = 0; ks < nk; ks++) {
        const uint32_t bufOff = (uint32_t)((ks & 1) * G_SBUF);
        if (ks + 1 < nk) {
            const uint32_t st = sbase + (uint32_t)(((ks + 1) & 1) * G_SBUF);
            const int k0 = (ks + 1) * 32;
#pragma unroll
            for (int p = 0; p < 2; p++) {
                const int row = sr0 + p * 64;
                const uint32_t d = st + (uint32_t)(row * 80 + su * 16);
                const size_t ra = (size_t)(row0 + row) * K + k0 + su * 8;
                const size_t rb = (size_t)(col0 + row) * K + k0 + su * 8;
                CP16(d + G_AH, &Ah[ra]);
                CP16(d + G_AL, &Al[ra]);
                CP16(d + G_BH, &Bh[rb]);
                CP16(d + G_BL, &Bl[rb]);
            }
            CP_COMMIT();
            CP_WAIT(1);
        } else {
            CP_WAIT(0);
        }
        __syncthreads();

#pragma unroll
        for (int kc = 0; kc < 2; kc++) {
            const uint32_t kadd = bufOff + (uint32_t)(kc * 32);
            uint32_t ah[2][4], al[2][4], bh[8][2], bl[8][2];
#pragma unroll
            for (int mt = 0; mt < 2; mt++) {
                LDSM_X4(ah[mt][0], ah[mt][1], ah[mt][2], ah[mt][3],
                        aHi0 + (uint32_t)(mt * 16 * 80) + kadd);
                LDSM_X4(al[mt][0], al[mt][1], al[mt][2], al[mt][3],
                        aLo0 + (uint32_t)(mt * 16 * 80) + kadd);
            }
#pragma unroll
            for (int g = 0; g < 4; g++) {
                uint32_t t0, t1, t2, t3;
                LDSM_X4(t0, t1, t2, t3, bHi0 + (uint32_t)(g * 16 * 80) + kadd);
                bh[2 * g][0] = t0; bh[2 * g][1] = t1;
                bh[2 * g + 1][0] = t2; bh[2 * g + 1][1] = t3;
                LDSM_X4(t0, t1, t2, t3, bLo0 + (uint32_t)(g * 16 * 80) + kadd);
                bl[2 * g][0] = t0; bl[2 * g][1] = t1;
                bl[2 * g + 1][0] = t2; bl[2 * g + 1][1] = t3;
            }
#pragma unroll
            for (int mt = 0; mt < 2; mt++)
#pragma unroll
                for (int j = 0; j < 8; j++)
                    MMA_BF16(acc[mt][j], ah[mt], bh[j][0], bh[j][1]);
#pragma unroll
            for (int mt = 0; mt < 2; mt++)
#pragma unroll
                for (int j = 0; j < 8; j++)
                    MMA_BF16(acc[mt][j], ah[mt], bl[j][0], bl[j][1]);
#pragma unroll
            for (int mt = 0; mt < 2; mt++)
#pragma unroll
                for (int j = 0; j < 8; j++)
                    MMA_BF16(acc[mt][j], al[mt], bh[j][0], bh[j][1]);
        }
        __syncthreads();
    }

    const int mrow = row0 + wm * 32 + (lane >> 2);
    const int ncol = col0 + wn * 64 + (lane & 3) * 2;
#pragma unroll
    for (int mt = 0; mt < 2; mt++) {
        const int r_up = mrow + mt * 16;
#pragma unroll
        for (int j = 0; j < 8; j++) {
            const int c = ncol + j * 8;
            const float b0 = bias[c], b1 = bias[c + 1];
            float2 v0 = make_float2(acc[mt][j][0] + b0, acc[mt][j][1] + b1);
            float2 v1 = make_float2(acc[mt][j][2] + b0, acc[mt][j][3] + b1);
            *reinterpret_cast<float2*>(&C[(size_t)r_up * Nc + c]) = v0;
            *reinterpret_cast<float2*>(&C[(size_t)(r_up + 8) * Nc + c]) = v1;
        }
    }
}

// ---------------------------------------------------------------------------
// Tensor-core flash attention.
// S = Qh.Kh + Qh.Kl (2 passes); PV = P x Vh (1 pass).
// Dynamic smem: Q (9216) + 2 bufs x (3 x 9216) = 64512B -> 3 CTAs/SM.
// ---------------------------------------------------------------------------
#define AROW 72
#define ARS  144
#define A_QH 0
#define A_KV 9216
#define A_KH 0
#define A_KL 9216
#define A_VH 18432
#define A_VBUF 27648
#define A_SMEM (A_KV + 2 * A_VBUF)   // 64512

__global__ __launch_bounds__(128)
void attn_tc(const __half* __restrict__ qh,
             const __half* __restrict__ kh, const __half* __restrict__ kl,
             const __half* __restrict__ vh,
             const int* __restrict__ t_idx,
             const unsigned char* __restrict__ mask,
             const float* __restrict__ alpha,
             __nv_bfloat16* __restrict__ ctxh, __nv_bfloat16* __restrict__ ctxl) {
    extern __shared__ char dsm[];
    __shared__ int tks2[2][64];
    const uint32_t sbase = smem_u32(dsm);

    const int qt = blockIdx.x, h = blockIdx.y, b = blockIdx.z;
    const int tid = threadIdx.x, warp = tid >> 5, lane = tid & 31;
    const int q0 = qt * 64;

    const float a_h = alpha[h];
    const size_t bn0 = (size_t)(b * Nn);
    const size_t hb = (size_t)(b * Hh + h) * HSZ;

    const int sr0 = tid >> 3, su = tid & 7;

    // ---- stage Q once ----
#pragma unroll
    for (int p = 0; p < 4; p++) {
        const int idx = p * 128 + tid;
        const int row = idx >> 3, u = idx & 7;
        const size_t src = hb + (size_t)(q0 + row) * HD + u * 8;
        *reinterpret_cast<uint4*>(dsm + A_QH + row * ARS + u * 16) =
            *reinterpret_cast<const uint4*>(&qh[src]);
    }

    const int g8 = lane >> 2;
    const int row_lo = q0 + warp * 16 + g8;
    const int row_hi = row_lo + 8;
    const float tq0 = (float)t_idx[bn0 + row_lo];
    const float tq1 = (float)t_idx[bn0 + row_hi];

    float ctxacc[8][4];
#pragma unroll
    for (int j = 0; j < 8; j++)
#pragma unroll
        for (int e = 0; e < 4; e++) ctxacc[j][e] = 0.0f;
    float lsum0 = 0.0f, lsum1 = 0.0f;
    float m0 = -1e30f, m1 = -1e30f;

    const int quad = lane >> 3, r8 = lane & 7;
    const uint32_t offA = (uint32_t)(((quad & 1) * 8 + r8) * ARS + ((quad >> 1) * 8) * 2);
    const uint32_t offB = (uint32_t)(((quad >> 1) * 8 + r8) * ARS + ((quad & 1) * 8) * 2);
    const uint32_t aQh = sbase + A_QH + (uint32_t)(warp * 16 * ARS) + offA;

    // ---- prologue: prefetch K/V tile 0; stage tks(0) ----
    {
        const uint32_t st = sbase + A_KV;
#pragma unroll
        for (int p = 0; p < 4; p++) {
            const int row = sr0 + p * 16;
            const uint32_t d = st + (uint32_t)(row * ARS + su * 16);
            const size_t srcK = hb + (size_t)row * HD + su * 8;
            const size_t srcV = hb + (size_t)row * Nn + su * 8;
            CP16(d + A_KH, &kh[srcK]);
            CP16(d + A_KL, &kl[srcK]);
            CP16(d + A_VH, &vh[srcV]);
        }
        CP_COMMIT();
        if (tid < 64) tks2[0][tid] = t_idx[bn0 + tid];
    }

    for (int it = 0; it < Nn / 64; it++) {
        const int k0 = it * 64;
        const uint32_t kvOff = (uint32_t)((it & 1) * A_VBUF);

        if (it + 1 < Nn / 64) {
            const int kn = (it + 1) * 64;
            const uint32_t st = sbase + A_KV + (uint32_t)(((it + 1) & 1) * A_VBUF);
#pragma unroll
            for (int p = 0; p < 4; p++) {
                const int row = sr0 + p * 16;
                const uint32_t d = st + (uint32_t)(row * ARS + su * 16);
                const size_t srcK = hb + (size_t)(kn + row) * HD + su * 8;
                const size_t srcV = hb + (size_t)row * Nn + kn + su * 8;
                CP16(d + A_KH, &kh[srcK]);
                CP16(d + A_KL, &kl[srcK]);
                CP16(d + A_VH, &vh[srcV]);
            }
            CP_COMMIT();
            if (tid < 64) tks2[(it + 1) & 1][tid] = t_idx[bn0 + kn + tid];
        }

        int myMask;
        {
            const int row = tid >> 1, half = tid & 1;
            const uint4* mp = reinterpret_cast<const uint4*>(
                &mask[(bn0 + q0 + row) * Nn + k0 + half * 32]);
            uint4 mA = mp[0], mB = mp[1];
            myMask = (mA.x | mA.y | mA.z | mA.w | mB.x | mB.y | mB.z | mB.w) != 0;
        }

        if (it + 1 < Nn / 64) { CP_WAIT(1); } else { CP_WAIT(0); }
        const int tileMasked = __syncthreads_or(myMask);

        const uint32_t bKh = sbase + A_KV + kvOff + A_KH + offB;
        const uint32_t bKl = sbase + A_KV + kvOff + A_KL + offB;
        const uint32_t bVh = sbase + A_KV + kvOff + A_VH + offB;
        const int* tks = tks2[it & 1];

        // ---- S = Qh.Kh + Qh.Kl ----
        float sacc[8][4];
#pragma unroll
        for (int j = 0; j < 8; j++)
#pragma unroll
            for (int e = 0; e < 4; e++) sacc[j][e] = 0.0f;

#pragma unroll
        for (int pass = 0; pass < 2; pass++) {
            const uint32_t bBase = (pass == 1) ? bKl : bKh;
#pragma unroll
            for (int kc = 0; kc < 4; kc++) {
                uint32_t aq[4];
                LDSM_X4(aq[0], aq[1], aq[2], aq[3], aQh + (uint32_t)(kc * 32));
#pragma unroll
                for (int g = 0; g < 4; g++) {
                    uint32_t t0, t1, t2, t3;
                    LDSM_X4(t0, t1, t2, t3, bBase + (uint32_t)(g * 16 * ARS + kc * 32));
                    MMA_FP16(sacc[2 * g], aq, t0, t1);
                    MMA_FP16(sacc[2 * g + 1], aq, t2, t3);
                }
            }
        }

        // ---- bias + tile max ----
        float tmax0 = -1e30f, tmax1 = -1e30f;
#pragma unroll
        for (int j = 0; j < 8; j++) {
            const int c0 = 8 * j + 2 * (lane & 3);
            const float tk0 = (float)tks[c0];
            const float tk1 = (float)tks[c0 + 1];
            sacc[j][0] -= a_h * fmaxf(tq0 - tk0, 0.0f);
            sacc[j][1] -= a_h * fmaxf(tq0 - tk1, 0.0f);
            sacc[j][2] -= a_h * fmaxf(tq1 - tk0, 0.0f);
            sacc[j][3] -= a_h * fmaxf(tq1 - tk1, 0.0f);
            tmax0 = fmaxf(tmax0, fmaxf(sacc[j][0], sacc[j][1]));
            tmax1 = fmaxf(tmax1, fmaxf(sacc[j][2], sacc[j][3]));
        }
        tmax0 = fmaxf(tmax0, __shfl_xor_sync(0xFFFFFFFF, tmax0, 1));
        tmax0 = fmaxf(tmax0, __shfl_xor_sync(0xFFFFFFFF, tmax0, 2));
        tmax1 = fmaxf(tmax1, __shfl_xor_sync(0xFFFFFFFF, tmax1, 1));
        tmax1 = fmaxf(tmax1, __shfl_xor_sync(0xFFFFFFFF, tmax1, 2));

        const float mn0 = fmaxf(m0, tmax0);
        const float mn1 = fmaxf(m1, tmax1);
        const float sc0 = __expf(m0 - mn0);
        const float sc1 = __expf(m1 - mn1);
        m0 = mn0; m1 = mn1;
        lsum0 *= sc0; lsum1 *= sc1;
#pragma unroll
        for (int j = 0; j < 8; j++) {
            ctxacc[j][0] *= sc0; ctxacc[j][1] *= sc0;
            ctxacc[j][2] *= sc1; ctxacc[j][3] *= sc1;
        }

        // ---- exp + mask + pack P ----
        uint32_t pa[4][4];
#pragma unroll
        for (int j = 0; j < 8; j++) {
            const int c0 = 8 * j + 2 * (lane & 3);
            float p0 = __expf(sacc[j][0] - m0);
            float p1 = __expf(sacc[j][1] - m0);
            float p2 = __expf(sacc[j][2] - m1);
            float p3 = __expf(sacc[j][3] - m1);
            if (tileMasked) {
                const unsigned char* mr0 = &mask[(bn0 + row_lo) * Nn + k0 + c0];
                const unsigned char* mr1 = &mask[(bn0 + row_hi) * Nn + k0 + c0];
                p0 = mr0[0] ? 0.0f : p0;
                p1 = mr0[1] ? 0.0f : p1;
                p2 = mr1[0] ? 0.0f : p2;
                p3 = mr1[1] ? 0.0f : p3;
            }
            const __half2 lo_h = __float22half2_rn(make_float2(p0, p1));
            const __half2 hi_h = __float22half2_rn(make_float2(p2, p3));
            const float2 lo_r = __half22float2(lo_h);
            const float2 hi_r = __half22float2(hi_h);
            lsum0 += lo_r.x + lo_r.y;
            lsum1 += hi_r.x + hi_r.y;
            pa[j >> 1][(j & 1) * 2 + 0] = h2_as_u32(lo_h);
            pa[j >> 1][(j & 1) * 2 + 1] = h2_as_u32(hi_h);
        }

        // ---- ctx += P x Vh ----
#pragma unroll
        for (int kc = 0; kc < 4; kc++) {
#pragma unroll
            for (int g = 0; g < 4; g++) {
                uint32_t t0, t1, t2, t3;
                LDSM_X4(t0, t1, t2, t3, bVh + (uint32_t)(g * 16 * ARS + kc * 32));
                MMA_FP16(ctxacc[2 * g], pa[kc], t0, t1);
                MMA_FP16(ctxacc[2 * g + 1], pa[kc], t2, t3);
            }
        }
        __syncthreads();
    }

    lsum0 += __shfl_xor_sync(0xFFFFFFFF, lsum0, 1);
    lsum0 += __shfl_xor_sync(0xFFFFFFFF, lsum0, 2);
    lsum1 += __shfl_xor_sync(0xFFFFFFFF, lsum1, 1);
    lsum1 += __shfl_xor_sync(0xFFFFFFFF, lsum1, 2);
    const float inv0 = (lsum0 > 0.0f) ? (1.0f / lsum0) : 0.0f;
    const float inv1 = (lsum1 > 0.0f) ? (1.0f / lsum1) : 0.0f;

#pragma unroll
    for (int j = 0; j < 8; j++) {
        const int c0 = h * HD + 8 * j + 2 * (lane & 3);
        const float o0 = ctxacc[j][0] * inv0, o1 = ctxacc[j][1] * inv0;
        const float o2 = ctxacc[j][2] * inv1, o3 = ctxacc[j][3] * inv1;
        __nv_bfloat16 h0 = __float2bfloat16_rn(o0), h1 = __float2bfloat16_rn(o1);
        __nv_bfloat16 h2 = __float2bfloat16_rn(o2), h3 = __float2bfloat16_rn(o3);
        __nv_bfloat162 hl; hl.x = h0; hl.y = h1;
        __nv_bfloat162 hh; hh.x = h2; hh.y = h3;
        __nv_bfloat162 ll; ll.x = __float2bfloat16_rn(o0 - __bfloat162float(h0));
        ll.y = __float2bfloat16_rn(o1 - __bfloat162float(h1));
        __nv_bfloat162 lh; lh.x = __float2bfloat16_rn(o2 - __bfloat162float(h2));
        lh.y = __float2bfloat16_rn(o3 - __bfloat162float(h3));
        *reinterpret_cast<__nv_bfloat162*>(&ctxh[(bn0 + row_lo) * Dd + c0]) = hl;
        *reinterpret_cast<__nv_bfloat162*>(&ctxh[(bn0 + row_hi) * Dd + c0]) = hh;
        *reinterpret_cast<__nv_bfloat162*>(&ctxl[(bn0 + row_lo) * Dd + c0]) = ll;
        *reinterpret_cast<__nv_bfloat162*>(&ctxl[(bn0 + row_hi) * Dd + c0]) = lh;
    }
}

// ---------------------------------------------------------------------------
extern "C" void kernel_launch(void* const* d_in, const int* in_sizes, int n_in,
                              void* d_out, int out_size) {
    const float*         X     = (const float*)d_in[0];
    const int*           t_idx = (const int*)d_in[1];
    const unsigned char* mask  = (const unsigned char*)d_in[2];
    const float*         Wqkv  = (const float*)d_in[3];
    const float*         bqkv  = (const float*)d_in[4];
    const float*         Wo    = (const float*)d_in[5];
    const float*         bo    = (const float*)d_in[6];
    const float*         alpha = (const float*)d_in[7];
    float*               out   = (float*)d_out;

    void *qkv_p, *xh_p, *xl_p, *wqh_p, *wql_p, *woh_p, *wol_p, *ctxh_p, *ctxl_p;
    void *qh_p, *kh_p, *kl_p, *vh_p;
    cudaGetSymbolAddress(&qkv_p, g_qkv);
    cudaGetSymbolAddress(&xh_p, g_xh);   cudaGetSymbolAddress(&xl_p, g_xl);
    cudaGetSymbolAddress(&wqh_p, g_wqh); cudaGetSymbolAddress(&wql_p, g_wql);
    cudaGetSymbolAddress(&woh_p, g_woh); cudaGetSymbolAddress(&wol_p, g_wol);
    cudaGetSymbolAddress(&ctxh_p, g_ctxh); cudaGetSymbolAddress(&ctxl_p, g_ctxl);
    cudaGetSymbolAddress(&qh_p, g_q16h);
    cudaGetSymbolAddress(&kh_p, g_k16h); cudaGetSymbolAddress(&kl_p, g_k16l);
    cudaGetSymbolAddress(&vh_p, g_v16h);

    cudaFuncSetAttribute(gemm_sp, cudaFuncAttributeMaxDynamicSharedMemorySize, G_SMEM);
    cudaFuncSetAttribute(attn_tc, cudaFuncAttributeMaxDynamicSharedMemorySize, A_SMEM);

    // prep1: split X, Wqkv, Wo
    split_bf16<<<(BN_ROWS * Dd / 4 + 255) / 256, 256>>>(
        X, (__nv_bfloat16*)xh_p, (__nv_bfloat16*)xl_p, BN_ROWS * Dd / 4);
    split_bf16<<<(QKV_COLS * Dd / 4 + 255) / 256, 256>>>(
        Wqkv, (__nv_bfloat16*)wqh_p, (__nv_bfloat16*)wql_p, QKV_COLS * Dd / 4);
    split_bf16<<<(Dd * Dd / 4 + 255) / 256, 256>>>(
        Wo, (__nv_bfloat16*)woh_p, (__nv_bfloat16*)wol_p, Dd * Dd / 4);

    // 1) QKV projection
    {
        dim3 grid(QKV_COLS / 128, BN_ROWS / 128);
        gemm_sp<<<grid, 256, G_SMEM>>>((__nv_bfloat16*)xh_p, (__nv_bfloat16*)xl_p,
                                       (__nv_bfloat16*)wqh_p, (__nv_bfloat16*)wql_p,
                                       bqkv, (float*)qkv_p, QKV_COLS, Dd);
    }

    // prep2: per-head fp16 (Qh, Kh+Kl, Vh transposed)
    {
        dim3 grid(Nn / 64, NH);
        attn_prep<<<grid, 128>>>((const float*)qkv_p,
                                 (__half*)qh_p,
                                 (__half*)kh_p, (__half*)kl_p,
                                 (__half*)vh_p);
    }

    // 2) Tensor-core flash attention -> ctx (bf16 hi/lo)
    {
        dim3 grid(Nn / 64, Hh, Bb);
        attn_tc<<<grid, 128, A_SMEM>>>((const __half*)qh_p,
                                       (const __half*)kh_p, (const __half*)kl_p,
                                       (const __half*)vh_p,
                                       t_idx, mask, alpha,
                                       (__nv_bfloat16*)ctxh_p, (__nv_bfloat16*)ctxl_p);
    }

    // 3) Output projection
    {
        dim3 grid(Dd / 128, BN_ROWS / 128);
        gemm_sp<<<grid, 256, G_SMEM>>>((__nv_bfloat16*)ctxh_p, (__nv_bfloat16*)ctxl_p,
                                       (__nv_bfloat16*)woh_p, (__nv_bfloat16*)wol_p,
                                       bo, out, Dd, Dd);
    }
}